// round 11
// baseline (speedup 1.0000x reference)
#include <cuda_runtime.h>
#include <cuda_fp16.h>
#include <cstdint>

#define BATCH 16
#define CIN   128
#define HGT   64
#define WID   384
#define F1C   128
#define F2C   96

#define TW     64
#define TH     2
#define ICB    16
#define NCHUNK (CIN/ICB)     // 8
#define INROWS (TH+2)        // 4
#define INCOLS (TW+2)        // 66
#define CSTRIDE 24           // fp16 per site (48B, conflict-free ldmatrix phases)
#define SIN_H  (INROWS*INCOLS*CSTRIDE)   // 6336 halves
#define NSTAGE (ICB*INROWS*INCOLS)       // 4224 elements per input chunk

#define NSITES (BATCH*HGT*WID)
#define WFOLD_BLOCKS 576                 // ceil(8*9*16*128/256)

// ---------------- device globals ----------------
__device__ __half g_h1[(size_t)NSITES * F1C];   // conv1 out, NHWC fp16
__device__ __half g_w1[NCHUNK * 9 * ICB * F1C]; // [chunk][tap][ic][oc]
__device__ __half g_w2[NCHUNK * 9 * ICB * F2C];
__device__ float g_s0[CIN], g_t0[CIN];
__device__ float g_s1[F1C], g_d1[F1C];
__device__ float g_s2[F2C], g_d2[F2C];
__device__ float g_sf1;

// ---------------- asm helpers ----------------
__device__ __forceinline__ void ldsm_x4(uint32_t* r, uint32_t addr) {
    asm volatile("ldmatrix.sync.aligned.m8n8.x4.shared.b16 {%0,%1,%2,%3}, [%4];\n"
                 : "=r"(r[0]), "=r"(r[1]), "=r"(r[2]), "=r"(r[3]) : "r"(addr));
}
__device__ __forceinline__ void ldsm_x4t(uint32_t* r, uint32_t addr) {
    asm volatile("ldmatrix.sync.aligned.m8n8.x4.trans.shared.b16 {%0,%1,%2,%3}, [%4];\n"
                 : "=r"(r[0]), "=r"(r[1]), "=r"(r[2]), "=r"(r[3]) : "r"(addr));
}
__device__ __forceinline__ void mma16816(float* c, const uint32_t* a, const uint32_t* b) {
    asm volatile("mma.sync.aligned.m16n8k16.row.col.f32.f16.f16.f32 "
                 "{%0,%1,%2,%3}, {%4,%5,%6,%7}, {%8,%9}, {%0,%1,%2,%3};\n"
                 : "+f"(c[0]), "+f"(c[1]), "+f"(c[2]), "+f"(c[3])
                 : "r"(a[0]), "r"(a[1]), "r"(a[2]), "r"(a[3]), "r"(b[0]), "r"(b[1]));
}
__device__ __forceinline__ void cp16(uint32_t dst, const void* src, bool pred) {
    int sz = pred ? 16 : 0;
    asm volatile("cp.async.cg.shared.global [%0], [%1], 16, %2;\n"
                 :: "r"(dst), "l"(src), "r"(sz));
}
__device__ __forceinline__ void cp_commit() {
    asm volatile("cp.async.commit_group;\n" ::: "memory");
}
__device__ __forceinline__ void cp_wait0() {
    asm volatile("cp.async.wait_group 0;\n" ::: "memory");
}

// ---------------- prep: fold scalars + transpose weights to fp16 ----------------
__global__ void prep_w(const float* __restrict__ Wv,
                       const float* __restrict__ bn0_g, const float* __restrict__ bn0_b,
                       const float* __restrict__ bn0_m, const float* __restrict__ bn0_v,
                       const float* __restrict__ w1raw, const float* __restrict__ conv1_b,
                       const float* __restrict__ bn1_g, const float* __restrict__ bn1_b,
                       const float* __restrict__ bn1_m, const float* __restrict__ bn1_v,
                       const float* __restrict__ w2raw, const float* __restrict__ conv2_b,
                       const float* __restrict__ bn2_g, const float* __restrict__ bn2_b,
                       const float* __restrict__ bn2_m, const float* __restrict__ bn2_v)
{
    const int bid = blockIdx.x;
    const int tid = threadIdx.x;

    if (bid == 0 && tid < 128) {
        const int c = tid;
        float w0 = Wv[0], w1 = Wv[1];
        float mx = fmaxf(w0, w1);
        float e0 = expf(w0 - mx), e1 = expf(w1 - mx);
        float inv = 1.f / (e0 + e1);
        float sf0 = e0 * inv, sf1 = e1 * inv;
        if (c == 0) g_sf1 = sf1;
        {
            float s = bn0_g[c] * rsqrtf(bn0_v[c] + 1e-5f);
            g_s0[c] = s;
            g_t0[c] = bn0_b[c] - bn0_m[c] * s;
            float s1 = bn1_g[c] * rsqrtf(bn1_v[c] + 1e-5f);
            g_s1[c] = s1;
            g_d1[c] = conv1_b[c] * s1 + bn1_b[c] - bn1_m[c] * s1;
        }
        if (c < F2C) {
            float s2 = bn2_g[c] * rsqrtf(bn2_v[c] + 1e-5f);
            g_s2[c] = s2 * sf0;
            g_d2[c] = (conv2_b[c] * s2 + bn2_b[c] - bn2_m[c] * s2) * sf0;
        }
    }
    const int i = bid * 256 + tid;
    const int n1 = NCHUNK * 9 * ICB * F1C;
    if (i < n1) {
        int oc = i % F1C; int r = i / F1C;
        int ic = r % ICB; r /= ICB;
        int tap = r % 9;  int chunk = r / 9;
        g_w1[i] = __float2half(w1raw[((size_t)oc * CIN + chunk * ICB + ic) * 9 + tap]);
    }
    const int n2 = NCHUNK * 9 * ICB * F2C;
    if (i < n2) {
        int oc = i % F2C; int r = i / F2C;
        int ic = r % ICB; r /= ICB;
        int tap = r % 9;  int chunk = r / 9;
        g_w2[i] = __float2half(w2raw[((size_t)oc * F1C + chunk * ICB + ic) * 9 + tap]);
    }
}

// ---------------- implicit-GEMM conv via mma.sync ----------------
// Block: 128 px (2 rows x 64 cols) x OC, 8 warps (4 M x 2 N).
// FIRST: stage fp32 NCHW x through registers, fusing bn0+relu+cvt; single cooked
//        input buffer, cp.async double-buffered weights; epilogue bn1+relu -> g_h1.
// !FIRST: round-7 path (NHWC fp16 g_h1 via cp.async, double-buffered); epilogue
//        bn2*sf0 + static-mask skip gather -> fp32 NCHW out.
template<int OC, int OCP, bool FIRST>
__global__ void __launch_bounds__(256, 2)
conv_mma(const __half* __restrict__ gin, const float* __restrict__ xf32,
         float* __restrict__ outf)
{
    extern __shared__ __half smem[];
    constexpr int SWH    = 9 * ICB * OCP;        // weight halves per buffer
    constexpr int NINBUF = FIRST ? 1 : 2;
    constexpr int NT8    = (OC / 2) / 8;
    constexpr int NG     = NT8 / 2;

    const int tid  = threadIdx.x;
    const int lane = tid & 31;
    const int warp = tid >> 5;
    const int wm   = warp & 3;
    const int wn   = warp >> 2;

    const int b  = blockIdx.z;
    const int h0 = blockIdx.y * TH;
    const int w0 = blockIdx.x * TW;

    const uint32_t s_base = (uint32_t)__cvta_generic_to_shared(smem);
    const uint32_t W_BASE = (uint32_t)(NINBUF * SIN_H * 2);

    float c[2][NT8][4];
    #pragma unroll
    for (int mt = 0; mt < 2; mt++)
        #pragma unroll
        for (int nt = 0; nt < NT8; nt++)
            #pragma unroll
            for (int k = 0; k < 4; k++) c[mt][nt][k] = 0.f;

    uint32_t a_base[2];
    #pragma unroll
    for (int mt = 0; mt < 2; mt++) {
        int pxb = wm * 32 + mt * 16;
        int r = pxb >> 6, cl = pxb & 63;
        a_base[mt] = s_base +
            (((r * INCOLS + cl + (lane & 15)) * CSTRIDE) + ((lane >> 4) << 3)) * 2;
    }
    const uint32_t b_base = s_base + W_BASE +
        (((lane & 15) * OCP) + wn * (OC / 2) + ((lane >> 4) << 3)) * 2;

    const __half* wbase = FIRST ? g_w1 : g_w2;

    // ---- weight staging (both paths) ----
    auto stage_w = [&](int cc, int buf) {
        const uint32_t wb = s_base + W_BASE + (buf ? (uint32_t)(SWH * 2) : 0u);
        const __half* wsrc = wbase + (size_t)cc * 9 * ICB * OC;
        constexpr int WN = 9 * ICB * (OC / 8);
        #pragma unroll
        for (int e0 = 0; e0 < (WN + 255) / 256; e0++) {
            int e = tid + e0 * 256;
            if (e < WN) {
                int row = e / (OC / 8), cb = e - row * (OC / 8);
                cp16(wb + (uint32_t)((row * OCP + cb * 8) * 2), wsrc + row * OC + cb * 8, true);
            }
        }
    };

    // ---- conv2-style input staging (cp.async fp16 NHWC) ----
    auto stage_in16 = [&](int cc, int buf) {
        const uint32_t ib = s_base + (buf ? (uint32_t)(SIN_H * 2) : 0u);
        #pragma unroll
        for (int e0 = 0; e0 < 3; e0++) {
            int e = tid + e0 * 256;
            if (e < INROWS * INCOLS * 2) {
                int site = e >> 1, half = e & 1;
                int r  = site / INCOLS, cl = site - r * INCOLS;
                int gh = h0 - 1 + r, gw = w0 - 1 + cl;
                bool ok = ((unsigned)gh < (unsigned)HGT) && ((unsigned)gw < (unsigned)WID);
                const __half* src = gin +
                    ((size_t)((b * HGT + (ok ? gh : 0)) * WID + (ok ? gw : 0))) * CIN +
                    cc * ICB + half * 8;
                cp16(ib + (uint32_t)((site * CSTRIDE + half * 8) * 2), src, ok);
            }
        }
    };

    // ---- conv1 register staging of fp32 x with fused bn0+relu ----
    float rv[17];
    auto ldg_in = [&](int cc) {
        #pragma unroll
        for (int k = 0; k < 17; k++) {
            int e = tid + k * 256;
            float v = 0.f;
            if (e < NSTAGE) {
                int ic  = e / (INROWS * INCOLS);
                int rem = e - ic * (INROWS * INCOLS);
                int r   = rem / INCOLS;
                int cl  = rem - r * INCOLS;
                int gh = h0 - 1 + r, gw = w0 - 1 + cl;
                if ((unsigned)gh < (unsigned)HGT && (unsigned)gw < (unsigned)WID) {
                    int gic = cc * ICB + ic;
                    float xv = xf32[((size_t)(b * CIN + gic) * HGT + gh) * WID + gw];
                    v = fmaxf(0.f, fmaf(xv, g_s0[gic], g_t0[gic]));
                }
            }
            rv[k] = v;
        }
    };
    auto sts_in = [&]() {
        #pragma unroll
        for (int k = 0; k < 17; k++) {
            int e = tid + k * 256;
            if (e < NSTAGE) {
                int ic  = e / (INROWS * INCOLS);
                int rem = e - ic * (INROWS * INCOLS);
                int r   = rem / INCOLS;
                int cl  = rem - r * INCOLS;
                smem[(r * INCOLS + cl) * CSTRIDE + ic] = __float2half(rv[k]);
            }
        }
    };

    // ---- compute one chunk ----
    auto compute = [&](int buf) {
        const uint32_t ioff = (!FIRST && buf) ? (uint32_t)(SIN_H * 2) : 0u;
        const uint32_t woff = buf ? (uint32_t)(SWH * 2) : 0u;
        #pragma unroll 3
        for (int tap = 0; tap < 9; tap++) {
            const int kh = tap / 3, kw = tap - kh * 3;
            const uint32_t aoff = (uint32_t)((kh * INCOLS + kw) * CSTRIDE * 2) + ioff;
            uint32_t a[2][4];
            ldsm_x4(a[0], a_base[0] + aoff);
            ldsm_x4(a[1], a_base[1] + aoff);

            uint32_t bw[NT8][2];
            const uint32_t boff = b_base + woff + (uint32_t)(tap * ICB * OCP * 2);
            #pragma unroll
            for (int g = 0; g < NG; g++)
                ldsm_x4t(&bw[2 * g][0], boff + (uint32_t)(g * 16 * 2));

            #pragma unroll
            for (int mt = 0; mt < 2; mt++)
                #pragma unroll
                for (int nt = 0; nt < NT8; nt++)
                    mma16816(c[mt][nt], a[mt], bw[nt]);
        }
    };

    // ---- mainloop ----
    if (FIRST) {
        ldg_in(0);
        stage_w(0, 0);
        cp_commit();
        #pragma unroll 1
        for (int cc = 0; cc < NCHUNK; cc++) {
            __syncthreads();              // compute(cc-1) finished reading cooked buffer
            sts_in();                     // cooked buffer = chunk cc
            cp_wait0();                   // weights chunk cc arrived
            __syncthreads();
            if (cc + 1 < NCHUNK) {
                ldg_in(cc + 1);           // long-latency LDGs overlap compute
                stage_w(cc + 1, (cc + 1) & 1);
                cp_commit();
            }
            compute(cc & 1);
        }
    } else {
        stage_in16(0, 0);
        stage_w(0, 0);
        cp_commit();
        #pragma unroll 1
        for (int cc = 0; cc < NCHUNK; cc++) {
            cp_wait0();
            __syncthreads();
            if (cc + 1 < NCHUNK) {
                stage_in16(cc + 1, (cc + 1) & 1);
                stage_w(cc + 1, (cc + 1) & 1);
                cp_commit();
            }
            compute(cc & 1);
        }
    }

    // ---- epilogue ----
    const int px0 = wm * 32;
    if (FIRST) {
        #pragma unroll
        for (int mt = 0; mt < 2; mt++) {
            #pragma unroll
            for (int nt = 0; nt < NT8; nt++) {
                const int oc = wn * (OC / 2) + nt * 8 + (lane & 3) * 2;
                const float s0v = g_s1[oc],     d0v = g_d1[oc];
                const float s1v = g_s1[oc + 1], d1v = g_d1[oc + 1];
                #pragma unroll
                for (int e = 0; e < 2; e++) {
                    int p = px0 + mt * 16 + (lane >> 2) + e * 8;
                    int r = p >> 6, cw = p & 63;
                    int gh = h0 + r, gw = w0 + cw;
                    float v0 = fmaxf(0.f, fmaf(c[mt][nt][2 * e],     s0v, d0v));
                    float v1 = fmaxf(0.f, fmaf(c[mt][nt][2 * e + 1], s1v, d1v));
                    *reinterpret_cast<__half2*>(
                        &g_h1[((size_t)((b * HGT + gh) * WID + gw)) * F1C + oc]) =
                        __floats2half2_rn(v0, v1);
                }
            }
        }
    } else {
        const float sf1 = g_sf1;
        #pragma unroll
        for (int mt = 0; mt < 2; mt++) {
            #pragma unroll
            for (int nt = 0; nt < NT8; nt++) {
                const int oc = wn * (OC / 2) + nt * 8 + (lane & 3) * 2;
                #pragma unroll
                for (int e = 0; e < 2; e++) {
                    int p = px0 + mt * 16 + (lane >> 2) + e * 8;
                    int r = p >> 6, cw = p & 63;
                    int gh = h0 + r, gw = w0 + cw;
                    #pragma unroll
                    for (int j = 0; j < 2; j++) {
                        int occ = oc + j;
                        int sc  = (occ / 3) * 4 + (occ % 3);    // static mask gather
                        float v = fmaf(c[mt][nt][2 * e + j], g_s2[occ], g_d2[occ]);
                        v += sf1 * xf32[((size_t)(b * CIN + sc) * HGT + gh) * WID + gw];
                        outf[((size_t)(b * OC + occ) * HGT + gh) * WID + gw] = v;
                    }
                }
            }
        }
    }
}

// ---------------- launch ----------------
extern "C" void kernel_launch(void* const* d_in, const int* in_sizes, int n_in,
                              void* d_out, int out_size)
{
    const float* x       = (const float*)d_in[0];
    const float* Wv      = (const float*)d_in[1];
    const float* bn0_g   = (const float*)d_in[2];
    const float* bn0_b   = (const float*)d_in[3];
    const float* bn0_m   = (const float*)d_in[4];
    const float* bn0_v   = (const float*)d_in[5];
    const float* conv1_w = (const float*)d_in[6];
    const float* conv1_b = (const float*)d_in[7];
    const float* bn1_g   = (const float*)d_in[8];
    const float* bn1_b   = (const float*)d_in[9];
    const float* bn1_m   = (const float*)d_in[10];
    const float* bn1_v   = (const float*)d_in[11];
    const float* conv2_w = (const float*)d_in[12];
    const float* conv2_b = (const float*)d_in[13];
    const float* bn2_g   = (const float*)d_in[14];
    const float* bn2_b   = (const float*)d_in[15];
    const float* bn2_m   = (const float*)d_in[16];
    const float* bn2_v   = (const float*)d_in[17];

    __half* h1 = nullptr;
    cudaGetSymbolAddress((void**)&h1, g_h1);

    const size_t smem1 = (size_t)(1 * SIN_H + 2 * 9 * ICB * 136) * 2;  //  91008 B
    const size_t smem2 = (size_t)(2 * SIN_H + 2 * 9 * ICB * 104) * 2;  //  85248 B
    cudaFuncSetAttribute(conv_mma<F1C, 136, true>,
                         cudaFuncAttributeMaxDynamicSharedMemorySize, (int)smem1);
    cudaFuncSetAttribute(conv_mma<F2C, 104, false>,
                         cudaFuncAttributeMaxDynamicSharedMemorySize, (int)smem2);

    prep_w<<<WFOLD_BLOCKS, 256>>>(
        Wv, bn0_g, bn0_b, bn0_m, bn0_v, conv1_w, conv1_b,
        bn1_g, bn1_b, bn1_m, bn1_v, conv2_w, conv2_b,
        bn2_g, bn2_b, bn2_m, bn2_v);

    dim3 grid(WID / TW, HGT / TH, BATCH);   // 6 x 32 x 16 = 3072
    conv_mma<F1C, 136, true ><<<grid, 256, smem1>>>(nullptr, x, nullptr);
    conv_mma<F2C, 104, false><<<grid, 256, smem2>>>(h1, x, (float*)d_out);
}